// round 14
// baseline (speedup 1.0000x reference)
#include <cuda_runtime.h>
#include <math.h>

// Problem constants
#define BATCH 8
#define FEAT  64
#define HW    262144             // 512*512
#define NSEG  33                 // ids 0..32 (0 = background)
#define NI    32

// Segment-max config (R7/R9-proven loop; only addition: L2 prefetch of tile u+1)
#define THREADS1 512             // 16 warps = 16 features per (b,fg) group
#define TILEPX   2048            // pixels per work unit
#define NTILE    (HW / TILEPX)   // 128
#define NU       (BATCH * 4 * NTILE)  // 4096 work units
#define NB       456             // 152 SMs * 3 CTAs, exact single wave

#define VEC_ELEMS (BATCH * NI * FEAT)   // 16384

// Per-(b,instance,feature) maxima as float bit patterns (nonneg -> int order ok).
// Statically zeroed; mlp kernel re-zeroes after consuming.
__device__ int g_scratch[VEC_ELEMS];
__device__ unsigned int g_cnt[BATCH];   // per-batch arrival tickets (zero-init, self-resetting)

extern __shared__ char smem_raw[];

// ---------------------------------------------------------------------------
// Kernel 1: persistent segment-max (R7 hot loop, byte-identical) + L2
// prefetch of the NEXT tile's enc plane and mask ids. Prefetches consume no
// data registers; loop LDGs become L2 hits -> in-flight requirement halves.
// ---------------------------------------------------------------------------
__global__ __launch_bounds__(THREADS1, 3)
void segmax_kernel(const float* __restrict__ enc,
                   const int*   __restrict__ masks) {
    float* s_acc = (float*)smem_raw;                          // 33*512 floats = 67584 B
    int*   s_ids = (int*)(smem_raw + NSEG * THREADS1 * 4);    // 2048 ints   =  8192 B

    const int tid  = threadIdx.x;
    const int lane = tid & 31;
    const int w    = tid >> 5;
    const int k    = blockIdx.x;

    const int s = (k * NU) / NB;
    const int e = ((k + 1) * NU) / NB;

    int cur = -1;
    int b = 0, f = 0;

    for (int u = s; u < e; ++u) {
        const int bfg = u >> 7;             // u / NTILE
        if (bfg != cur) {
            if (cur >= 0) {
                // flush: column tid is private to this thread; warp-reduce per id
                #pragma unroll
                for (int id = 1; id < NSEG; ++id) {
                    float v = s_acc[(id << 9) + tid];
                    #pragma unroll
                    for (int off = 16; off; off >>= 1)
                        v = fmaxf(v, __shfl_xor_sync(0xffffffffu, v, off));
                    if (lane == 0 && v > 0.0f)
                        atomicMax(&g_scratch[((b * NI) + (id - 1)) * FEAT + f],
                                  __float_as_int(v));
                }
            }
            #pragma unroll
            for (int r = 0; r < NSEG; ++r) s_acc[(r << 9) + tid] = 0.0f;
            cur = bfg;
            b = bfg >> 2;
            f = ((bfg & 3) << 4) | w;
        }
        const int tile = u & (NTILE - 1);

        // ---- L2 prefetch of tile u+1 (enc plane for this warp's next
        // feature + next mask tile). No data regs; wrong-stream prefetch at
        // bfg boundaries is rare and harmless. ----
        {
            const int un = u + 1;
            if (un < e) {
                const int bfg_n = un >> 7;
                const int bn = bfg_n >> 2;
                const int fn = ((bfg_n & 3) << 4) | w;
                const int tn = un & (NTILE - 1);
                const char* pe = (const char*)(enc
                                 + (size_t)(bn * FEAT + fn) * HW + tn * TILEPX)
                                 + lane * 256;
                asm volatile("prefetch.global.L2 [%0];" :: "l"(pe));
                asm volatile("prefetch.global.L2 [%0];" :: "l"(pe + 128));
                if (tid < 64) {
                    const char* pm = (const char*)(masks
                                     + (size_t)bn * HW + tn * TILEPX) + tid * 128;
                    asm volatile("prefetch.global.L2 [%0];" :: "l"(pm));
                }
            }
        }

        // Stage mask ids for this tile (premultiplied by 512 = row stride).
        __syncthreads();   // prior tile's s_ids consumers are done
        {
            const int4 m = ((const int4*)(masks + (size_t)b * HW + tile * TILEPX))[tid];
            ((int4*)s_ids)[tid] = make_int4(m.x << 9, m.y << 9, m.z << 9, m.w << 9);
        }
        __syncthreads();

        const float4* src4 = (const float4*)enc
                           + (size_t)(b * FEAT + f) * (HW / 4)
                           + tile * (TILEPX / 4);
        const int4* id4 = (const int4*)s_ids;

        #pragma unroll 4
        for (int g = 0; g < TILEPX / 4 / 32; ++g) {   // 16 iterations
            const int idx = g * 32 + lane;
            const float4 v = src4[idx];
            const int4  o = id4[idx];
            float a;
            a = s_acc[o.x + tid]; if (v.x > a) s_acc[o.x + tid] = v.x;
            a = s_acc[o.y + tid]; if (v.y > a) s_acc[o.y + tid] = v.y;
            a = s_acc[o.z + tid]; if (v.z > a) s_acc[o.z + tid] = v.z;
            a = s_acc[o.w + tid]; if (v.w > a) s_acc[o.w + tid] = v.w;
        }
    }

    // final flush
    #pragma unroll
    for (int id = 1; id < NSEG; ++id) {
        float v = s_acc[(id << 9) + tid];
        #pragma unroll
        for (int off = 16; off; off >>= 1)
            v = fmaxf(v, __shfl_xor_sync(0xffffffffu, v, off));
        if (lane == 0 && v > 0.0f)
            atomicMax(&g_scratch[((b * NI) + (id - 1)) * FEAT + f],
                      __float_as_int(v));
    }

#if __CUDA_ARCH__ >= 900
    cudaTriggerProgrammaticLaunchCompletion();
#endif
}

// ---------------------------------------------------------------------------
// Kernel 2: collapsed relation MLP (R9, unchanged): 152 blocks, PDL.
//   out[b,c,j,i] = sigmoid( v_i.(W1a W2) + v_j.(W1b W2) + (b1 W2 + b2) )
// ---------------------------------------------------------------------------
#define TH2    256
#define SLICES 19
#define OSLICE 216              // ceil(4096 / 19)

__global__ __launch_bounds__(TH2)
void mlp_kernel(const float* __restrict__ w1,
                const float* __restrict__ b1,
                const float* __restrict__ w2,
                const float* __restrict__ b2,
                float* __restrict__ out_vec,
                float* __restrict__ out_conn) {
    __shared__ float s_w1[128 * 32];   // 16 KB
    __shared__ float s_w2[32 * 4];
    __shared__ float s_b1[32];
    __shared__ float s_b2[4];
    __shared__ float s_m1[FEAT * 4];   // (W1a W2)[k][c]
    __shared__ float s_m2[FEAT * 4];   // (W1b W2)[k][c]
    __shared__ float s_c0[4];
    __shared__ float s_v[NI * 65];     // padded stride 65
    __shared__ float s_P[NI * 4];
    __shared__ float s_Q[NI * 4];
    __shared__ unsigned int s_rank;

    const int b   = blockIdx.x / SLICES;
    const int sl  = blockIdx.x % SLICES;
    const int tid = threadIdx.x;

    // ---- PDL prologue: depends ONLY on weight inputs (not on segmax) ----
    #pragma unroll
    for (int t = 0; t < 4; ++t)
        ((float4*)s_w1)[tid + t * TH2] = ((const float4*)w1)[tid + t * TH2];
    if (tid < 32) ((float4*)s_w2)[tid] = ((const float4*)w2)[tid];
    if (tid < 8)  ((float4*)s_b1)[tid] = ((const float4*)b1)[tid];
    if (tid < 4)  s_b2[tid] = b2[tid];
    __syncthreads();

    // fold: m1[k][c] = sum_m w1[k][m] w2[m][c]; m2 likewise for w1[64+k]
    {
        const int kk = tid >> 2, c = tid & 3;
        float a1 = 0.0f, a2 = 0.0f;
        #pragma unroll 8
        for (int m = 0; m < 32; ++m) {
            const float w2v = s_w2[m * 4 + c];
            a1 += s_w1[kk * 32 + m] * w2v;
            a2 += s_w1[(64 + kk) * 32 + m] * w2v;
        }
        s_m1[tid] = a1;
        s_m2[tid] = a2;
        if (tid < 4) {
            float a = s_b2[tid];
            #pragma unroll 8
            for (int m = 0; m < 32; ++m) a += s_b1[m] * s_w2[m * 4 + tid];
            s_c0[tid] = a;
        }
    }

    // ---- wait for segmax's scratch writes to be visible ----
#if __CUDA_ARCH__ >= 900
    cudaGridDependencySynchronize();
#endif

    #pragma unroll
    for (int t = tid; t < NI * FEAT; t += TH2)
        s_v[(t >> 6) * 65 + (t & 63)] = __int_as_float(g_scratch[b * NI * FEAT + t]);
    __syncthreads();

    // P[i][c] = v_i . m1_c ; Q[j][c] = v_j . m2_c
    {
        const int isQ = tid >> 7;
        const int idx = tid & 127;
        const int r = idx >> 2, c = idx & 3;
        const float* vm = s_v + r * 65;
        const float* mm = isQ ? s_m2 : s_m1;
        float a = 0.0f;
        #pragma unroll 8
        for (int kk = 0; kk < FEAT; ++kk) a += vm[kk] * mm[kk * 4 + c];
        if (isQ) s_Q[idx] = a;
        else     s_P[idx] = a;
    }
    __syncthreads();

    // this block's output slice: o in [sl*216, min(4096, sl*216+216))
    {
        const int o = sl * OSLICE + tid;
        if (tid < OSLICE && o < 4096) {      // o = c*1024 + j*32 + i
            const int c = o >> 10;
            const int j = (o >> 5) & 31;
            const int i = o & 31;
            const float t = s_P[i * 4 + c] + s_Q[j * 4 + c] + s_c0[c];
            out_conn[(size_t)b * 4096 + o] = 1.0f / (1.0f + __expf(-t));
        }
    }

    // last block of this batch writes vectors + re-zeroes scratch & ticket.
    __threadfence();
    if (tid == 0) s_rank = atomicAdd(&g_cnt[b], 1u);
    __syncthreads();
    if (s_rank == SLICES - 1) {
        #pragma unroll
        for (int t = tid; t < NI * FEAT; t += TH2) {
            const int gidx = b * NI * FEAT + t;
            out_vec[gidx]   = s_v[(t >> 6) * 65 + (t & 63)];
            g_scratch[gidx] = 0;
        }
        if (tid == 0) g_cnt[b] = 0;
    }
}

// ---------------------------------------------------------------------------
// Launch: segmax, then mlp with programmatic stream serialization (PDL).
// ---------------------------------------------------------------------------
extern "C" void kernel_launch(void* const* d_in, const int* in_sizes, int n_in,
                              void* d_out, int out_size) {
    const float* enc   = (const float*)d_in[0];
    const int*   masks = (const int*)d_in[1];
    const float* w1    = (const float*)d_in[2];
    const float* b1    = (const float*)d_in[3];
    const float* w2    = (const float*)d_in[4];
    const float* b2    = (const float*)d_in[5];

    float* out_vec  = (float*)d_out;
    float* out_conn = out_vec + VEC_ELEMS;

    static bool attr_set = false;
    const int smem_bytes = NSEG * THREADS1 * 4 + TILEPX * 4;  // 75776
    if (!attr_set) {
        cudaFuncSetAttribute(segmax_kernel,
                             cudaFuncAttributeMaxDynamicSharedMemorySize, smem_bytes);
        attr_set = true;
    }

    segmax_kernel<<<NB, THREADS1, smem_bytes>>>(enc, masks);

    cudaLaunchConfig_t cfg = {};
    cfg.gridDim  = dim3(BATCH * SLICES, 1, 1);
    cfg.blockDim = dim3(TH2, 1, 1);
    cfg.dynamicSmemBytes = 0;
    cudaLaunchAttribute attrs[1];
    attrs[0].id = cudaLaunchAttributeProgrammaticStreamSerialization;
    attrs[0].val.programmaticStreamSerializationAllowed = 1;
    cfg.attrs = attrs;
    cfg.numAttrs = 1;
    cudaLaunchKernelEx(&cfg, mlp_kernel, w1, b1, w2, b2, out_vec, out_conn);
}

// round 15
// speedup vs baseline: 1.4699x; 1.4699x over previous
#include <cuda_runtime.h>
#include <math.h>

// Problem constants
#define BATCH 8
#define FEAT  64
#define HW    262144             // 512*512
#define NSEG  33                 // ids 0..32 (0 = background)
#define NI    32

// Segment-max config (R2/R7-proven loop — DO NOT TOUCH)
#define THREADS1 512             // 16 warps = 16 features per (b,fg) group
#define TILEPX   2048            // pixels per work unit
#define NTILE    (HW / TILEPX)   // 128
#define NU       (BATCH * 4 * NTILE)  // 4096 work units
#define NB       456             // 152 SMs * 3 CTAs, exact single wave

#define VEC_ELEMS (BATCH * NI * FEAT)   // 16384

// Per-(b,instance,feature) maxima as float bit patterns (nonneg -> int order ok).
// Statically zeroed; mlp kernel re-zeroes after consuming, so every call sees
// identical initial state.
__device__ int g_scratch[VEC_ELEMS];
__device__ unsigned int g_cnt[BATCH];   // per-batch arrival tickets (zero-init, self-resetting)

extern __shared__ char smem_raw[];

// ---------------------------------------------------------------------------
// Kernel 1: persistent segment-max (R2 structure, measured ~99.7us).
// Block = 512 threads (16 warps); warp w <-> feature f = fg*16 + w.
// Per-thread private accumulators in smem: s_acc[id*512 + tid] (bank=tid%32,
// always conflict-free). Ids staged in smem premultiplied by 512.
// Conditional scalar max keeps the LSU instruction count minimal — the
// measured binding resource of this kernel.
// ---------------------------------------------------------------------------
__global__ __launch_bounds__(THREADS1, 3)
void segmax_kernel(const float* __restrict__ enc,
                   const int*   __restrict__ masks) {
    float* s_acc = (float*)smem_raw;                          // 33*512 floats = 67584 B
    int*   s_ids = (int*)(smem_raw + NSEG * THREADS1 * 4);    // 2048 ints   =  8192 B

    const int tid  = threadIdx.x;
    const int lane = tid & 31;
    const int w    = tid >> 5;
    const int k    = blockIdx.x;

    const int s = (k * NU) / NB;
    const int e = ((k + 1) * NU) / NB;

    int cur = -1;
    int b = 0, f = 0;

    for (int u = s; u < e; ++u) {
        const int bfg = u >> 7;             // u / NTILE
        if (bfg != cur) {
            if (cur >= 0) {
                // flush: column tid is private to this thread; warp-reduce per id
                #pragma unroll
                for (int id = 1; id < NSEG; ++id) {
                    float v = s_acc[(id << 9) + tid];
                    #pragma unroll
                    for (int off = 16; off; off >>= 1)
                        v = fmaxf(v, __shfl_xor_sync(0xffffffffu, v, off));
                    if (lane == 0 && v > 0.0f)
                        atomicMax(&g_scratch[((b * NI) + (id - 1)) * FEAT + f],
                                  __float_as_int(v));
                }
            }
            #pragma unroll
            for (int r = 0; r < NSEG; ++r) s_acc[(r << 9) + tid] = 0.0f;
            cur = bfg;
            b = bfg >> 2;
            f = ((bfg & 3) << 4) | w;
        }
        const int tile = u & (NTILE - 1);

        // Stage mask ids for this tile (premultiplied by 512 = row stride).
        __syncthreads();   // prior tile's s_ids consumers are done
        {
            const int4 m = ((const int4*)(masks + (size_t)b * HW + tile * TILEPX))[tid];
            ((int4*)s_ids)[tid] = make_int4(m.x << 9, m.y << 9, m.z << 9, m.w << 9);
        }
        __syncthreads();

        const float4* src4 = (const float4*)enc
                           + (size_t)(b * FEAT + f) * (HW / 4)
                           + tile * (TILEPX / 4);
        const int4* id4 = (const int4*)s_ids;

        #pragma unroll 4
        for (int g = 0; g < TILEPX / 4 / 32; ++g) {   // 16 iterations
            const int idx = g * 32 + lane;
            const float4 v = src4[idx];
            const int4  o = id4[idx];
            float a;
            a = s_acc[o.x + tid]; if (v.x > a) s_acc[o.x + tid] = v.x;
            a = s_acc[o.y + tid]; if (v.y > a) s_acc[o.y + tid] = v.y;
            a = s_acc[o.z + tid]; if (v.z > a) s_acc[o.z + tid] = v.z;
            a = s_acc[o.w + tid]; if (v.w > a) s_acc[o.w + tid] = v.w;
        }
    }

    // final flush
    #pragma unroll
    for (int id = 1; id < NSEG; ++id) {
        float v = s_acc[(id << 9) + tid];
        #pragma unroll
        for (int off = 16; off; off >>= 1)
            v = fmaxf(v, __shfl_xor_sync(0xffffffffu, v, off));
        if (lane == 0 && v > 0.0f)
            atomicMax(&g_scratch[((b * NI) + (id - 1)) * FEAT + f],
                      __float_as_int(v));
    }

#if __CUDA_ARCH__ >= 900
    cudaTriggerProgrammaticLaunchCompletion();
#endif
}

// ---------------------------------------------------------------------------
// Kernel 2: collapsed relation MLP (no nonlinearity between layers):
//   out[b,c,j,i] = sigmoid( v_i.(W1a W2) + v_j.(W1b W2) + (b1 W2 + b2) )
// 152 blocks (19 per batch) to clear the low-grid issue throttle; PDL so the
// weight-staging + fold prologue can overlap segmax's drain where possible.
// ---------------------------------------------------------------------------
#define TH2    256
#define SLICES 19
#define OSLICE 216              // ceil(4096 / 19)

__global__ __launch_bounds__(TH2)
void mlp_kernel(const float* __restrict__ w1,
                const float* __restrict__ b1,
                const float* __restrict__ w2,
                const float* __restrict__ b2,
                float* __restrict__ out_vec,
                float* __restrict__ out_conn) {
    __shared__ float s_w1[128 * 32];   // 16 KB
    __shared__ float s_w2[32 * 4];
    __shared__ float s_b1[32];
    __shared__ float s_b2[4];
    __shared__ float s_m1[FEAT * 4];   // (W1a W2)[k][c]
    __shared__ float s_m2[FEAT * 4];   // (W1b W2)[k][c]
    __shared__ float s_c0[4];
    __shared__ float s_v[NI * 65];     // padded stride 65
    __shared__ float s_P[NI * 4];
    __shared__ float s_Q[NI * 4];
    __shared__ unsigned int s_rank;

    const int b   = blockIdx.x / SLICES;
    const int sl  = blockIdx.x % SLICES;
    const int tid = threadIdx.x;

    // ---- PDL prologue: depends ONLY on weight inputs (not on segmax) ----
    #pragma unroll
    for (int t = 0; t < 4; ++t)
        ((float4*)s_w1)[tid + t * TH2] = ((const float4*)w1)[tid + t * TH2];
    if (tid < 32) ((float4*)s_w2)[tid] = ((const float4*)w2)[tid];
    if (tid < 8)  ((float4*)s_b1)[tid] = ((const float4*)b1)[tid];
    if (tid < 4)  s_b2[tid] = b2[tid];
    __syncthreads();

    // fold: m1[k][c] = sum_m w1[k][m] w2[m][c]; m2 likewise for w1[64+k]
    {
        const int kk = tid >> 2, c = tid & 3;
        float a1 = 0.0f, a2 = 0.0f;
        #pragma unroll 8
        for (int m = 0; m < 32; ++m) {
            const float w2v = s_w2[m * 4 + c];
            a1 += s_w1[kk * 32 + m] * w2v;
            a2 += s_w1[(64 + kk) * 32 + m] * w2v;
        }
        s_m1[tid] = a1;
        s_m2[tid] = a2;
        if (tid < 4) {
            float a = s_b2[tid];
            #pragma unroll 8
            for (int m = 0; m < 32; ++m) a += s_b1[m] * s_w2[m * 4 + tid];
            s_c0[tid] = a;
        }
    }

    // ---- wait for segmax's scratch writes to be visible ----
#if __CUDA_ARCH__ >= 900
    cudaGridDependencySynchronize();
#endif

    #pragma unroll
    for (int t = tid; t < NI * FEAT; t += TH2)
        s_v[(t >> 6) * 65 + (t & 63)] = __int_as_float(g_scratch[b * NI * FEAT + t]);
    __syncthreads();

    // P[i][c] = v_i . m1_c ; Q[j][c] = v_j . m2_c
    {
        const int isQ = tid >> 7;
        const int idx = tid & 127;
        const int r = idx >> 2, c = idx & 3;
        const float* vm = s_v + r * 65;
        const float* mm = isQ ? s_m2 : s_m1;
        float a = 0.0f;
        #pragma unroll 8
        for (int kk = 0; kk < FEAT; ++kk) a += vm[kk] * mm[kk * 4 + c];
        if (isQ) s_Q[idx] = a;
        else     s_P[idx] = a;
    }
    __syncthreads();

    // this block's output slice: o in [sl*216, min(4096, sl*216+216))
    {
        const int o = sl * OSLICE + tid;
        if (tid < OSLICE && o < 4096) {      // o = c*1024 + j*32 + i
            const int c = o >> 10;
            const int j = (o >> 5) & 31;
            const int i = o & 31;
            const float t = s_P[i * 4 + c] + s_Q[j * 4 + c] + s_c0[c];
            out_conn[(size_t)b * 4096 + o] = 1.0f / (1.0f + __expf(-t));
        }
    }

    // last block of this batch writes vectors + re-zeroes scratch & ticket.
    __threadfence();
    if (tid == 0) s_rank = atomicAdd(&g_cnt[b], 1u);
    __syncthreads();
    if (s_rank == SLICES - 1) {
        #pragma unroll
        for (int t = tid; t < NI * FEAT; t += TH2) {
            const int gidx = b * NI * FEAT + t;
            out_vec[gidx]   = s_v[(t >> 6) * 65 + (t & 63)];
            g_scratch[gidx] = 0;
        }
        if (tid == 0) g_cnt[b] = 0;
    }
}

// ---------------------------------------------------------------------------
// Launch: segmax, then mlp with programmatic stream serialization (PDL).
// ---------------------------------------------------------------------------
extern "C" void kernel_launch(void* const* d_in, const int* in_sizes, int n_in,
                              void* d_out, int out_size) {
    const float* enc   = (const float*)d_in[0];
    const int*   masks = (const int*)d_in[1];
    const float* w1    = (const float*)d_in[2];
    const float* b1    = (const float*)d_in[3];
    const float* w2    = (const float*)d_in[4];
    const float* b2    = (const float*)d_in[5];

    float* out_vec  = (float*)d_out;
    float* out_conn = out_vec + VEC_ELEMS;

    static bool attr_set = false;
    const int smem_bytes = NSEG * THREADS1 * 4 + TILEPX * 4;  // 75776
    if (!attr_set) {
        cudaFuncSetAttribute(segmax_kernel,
                             cudaFuncAttributeMaxDynamicSharedMemorySize, smem_bytes);
        attr_set = true;
    }

    segmax_kernel<<<NB, THREADS1, smem_bytes>>>(enc, masks);

    cudaLaunchConfig_t cfg = {};
    cfg.gridDim  = dim3(BATCH * SLICES, 1, 1);
    cfg.blockDim = dim3(TH2, 1, 1);
    cfg.dynamicSmemBytes = 0;
    cudaLaunchAttribute attrs[1];
    attrs[0].id = cudaLaunchAttributeProgrammaticStreamSerialization;
    attrs[0].val.programmaticStreamSerializationAllowed = 1;
    cfg.attrs = attrs;
    cfg.numAttrs = 1;
    cudaLaunchKernelEx(&cfg, mlp_kernel, w1, b1, w2, b2, out_vec, out_conn);
}